// round 6
// baseline (speedup 1.0000x reference)
#include <cuda_runtime.h>
#include <cuda_bf16.h>
#include <cstdint>

// BasicLSTM via mma.sync (HMMA bf16, 3-term fp32-split emulation).
// SEQ=512, BATCH=64, HID=1024, LAYERS=2.
// One persistent kernel, 128 CTAs (32 M-tiles x 4 K-slices), grid barriers.
// R6: 3-stage cp.async pipeline + cross-barrier W prefetch (fill the
// epilogue/cell bubble with next phase's weight loads).

#define SEQ    512
#define BATCH  64
#define HID    1024
#define KTOT   2048
#define NOUT   4096
#define BH     (BATCH * HID)        // 65536
#define NBLK   128
#define NTHR   256
#define GTH    (NBLK * NTHR)
#define NKS    4
#define KSL    512                  // K per slice
#define CHK    64                   // K per chunk
#define NCHK   (KSL / CHK)          // 8
#define STGB   49152                // Ahi16K | Alo16K | Bhi8K | Blo8K
#define NSTG   3
#define DSMEM  (NSTG * STGB)

// ---------------- device globals (no allocs) ----------------
// activations stored [feature k][batch b] (k-major) for ldmatrix.trans
__device__ __align__(128) __nv_bfloat16 g_xhi[(size_t)SEQ * HID * 64];
__device__ __align__(128) __nv_bfloat16 g_xlo[(size_t)SEQ * HID * 64];
__device__ __align__(128) __nv_bfloat16 g_wthi[(size_t)2 * NOUT * KTOT]; // [l][p][k]
__device__ __align__(128) __nv_bfloat16 g_wtlo[(size_t)2 * NOUT * KTOT];
__device__ __align__(128) __nv_bfloat16 g_hhi[4 * BH];   // [par*2+l][u][b]
__device__ __align__(128) __nv_bfloat16 g_hlo[4 * BH];
__device__ __align__(128) float g_partial[(size_t)NKS * NOUT * 64]; // [ks][p][b]
__device__ __align__(128) float g_c[2 * BH];              // [l][u][b]
__device__ __align__(128) float g_hf[4 * BH];             // [par*2+l][u][b]
__device__ unsigned g_bar_arrive;
__device__ unsigned g_bar_gen;

// ---------------- PTX helpers ----------------
__device__ __forceinline__ uint32_t smem_u32(const void* p) {
    uint32_t a;
    asm("{ .reg .u64 t; cvta.to.shared.u64 t, %1; cvt.u32.u64 %0, t; }"
        : "=r"(a) : "l"(p));
    return a;
}
__device__ __forceinline__ void cpa16(uint32_t s, const void* g) {
    asm volatile("cp.async.cg.shared.global [%0], [%1], 16;" :: "r"(s), "l"(g));
}
__device__ __forceinline__ void cpa_commit() {
    asm volatile("cp.async.commit_group;" ::: "memory");
}
__device__ __forceinline__ void cpa_wait2() {
    asm volatile("cp.async.wait_group 2;" ::: "memory");
}
__device__ __forceinline__ void cpa_wait1() {
    asm volatile("cp.async.wait_group 1;" ::: "memory");
}
__device__ __forceinline__ void cpa_wait0() {
    asm volatile("cp.async.wait_group 0;" ::: "memory");
}
__device__ __forceinline__ void ldsm4(uint32_t a, uint32_t& r0, uint32_t& r1,
                                      uint32_t& r2, uint32_t& r3) {
    asm volatile("ldmatrix.sync.aligned.m8n8.x4.shared.b16 {%0,%1,%2,%3}, [%4];"
                 : "=r"(r0), "=r"(r1), "=r"(r2), "=r"(r3) : "r"(a));
}
__device__ __forceinline__ void ldsm4t(uint32_t a, uint32_t& r0, uint32_t& r1,
                                       uint32_t& r2, uint32_t& r3) {
    asm volatile("ldmatrix.sync.aligned.m8n8.x4.trans.shared.b16 {%0,%1,%2,%3}, [%4];"
                 : "=r"(r0), "=r"(r1), "=r"(r2), "=r"(r3) : "r"(a));
}
__device__ __forceinline__ void mma16816(float* c, const uint32_t* a,
                                         uint32_t b0, uint32_t b1) {
    asm volatile("mma.sync.aligned.m16n8k16.row.col.f32.bf16.bf16.f32 "
                 "{%0,%1,%2,%3}, {%4,%5,%6,%7}, {%8,%9}, {%0,%1,%2,%3};"
                 : "+f"(c[0]), "+f"(c[1]), "+f"(c[2]), "+f"(c[3])
                 : "r"(a[0]), "r"(a[1]), "r"(a[2]), "r"(a[3]), "r"(b0), "r"(b1));
}
__device__ __forceinline__ float sigmoidf_(float x) { return 1.0f / (1.0f + expf(-x)); }
__device__ __forceinline__ void split1(float v, __nv_bfloat16& h, __nv_bfloat16& l) {
    h = __float2bfloat16_rn(v);
    l = __float2bfloat16_rn(v - __bfloat162float(h));
}
__device__ __forceinline__ uint32_t swz(uint32_t off) {
    return off ^ ((off >> 3) & 0x70);
}

// ---------------- grid barrier (all 128 blocks resident) ----------------
__device__ __forceinline__ void grid_barrier() {
    __syncthreads();
    if (threadIdx.x == 0) {
        __threadfence();
        unsigned gen = *((volatile unsigned*)&g_bar_gen);
        if (atomicAdd(&g_bar_arrive, 1u) == NBLK - 1) {
            g_bar_arrive = 0;
            __threadfence();
            atomicAdd(&g_bar_gen, 1u);
        } else {
            while (*((volatile unsigned*)&g_bar_gen) == gen) { __nanosleep(20); }
        }
        __threadfence();
    }
    __syncthreads();
}

// ---------------- persistent kernel ----------------
__global__ void __launch_bounds__(NTHR, 1)
lstm_hmma(const float* __restrict__ input,   // [512,64,1024]
          const float* __restrict__ h0,      // [2,64,1024]
          const float* __restrict__ c0,      // [2,64,1024]
          const float* __restrict__ W,       // [2,2048,4096]
          const float* __restrict__ bias,    // [2,4096]
          float* __restrict__ out)
{
    extern __shared__ __align__(1024) char dsm[];
    const uint32_t sbase = smem_u32(dsm);

    __shared__ float s_tr[32][33];
    __shared__ float s_hn[8][64];

    const int tid  = threadIdx.x;
    const int wid  = tid >> 5;
    const int lane = tid & 31;
    const int bid  = blockIdx.x;
    const int gid  = bid * NTHR + tid;
    const int cg   = bid & 31;        // M tile: rows [cg*128, +128)
    const int ks   = bid >> 5;        // K slice: [ks*512, +512)
    const int m0   = cg * 128;
    const int u0   = bid * 8;         // cell-owned units
    const int mw   = wid * 16;        // warp M strip within tile

    // ======== phase 0a: x transpose [t][b][u] -> [t][u][b] + bf16 split ====
    for (int tile = bid; tile < SEQ * 64; tile += NBLK) {
        const int t  = tile >> 6;
        const int ut = (tile >> 1) & 31;
        const int bt = tile & 1;
        const int ub = ut * 32, bb = bt * 32;
#pragma unroll
        for (int it = 0; it < 4; it++) {
            int r = (tid >> 5) + it * 8, c = tid & 31;
            s_tr[r][c] = input[((size_t)t * 64 + bb + r) * HID + ub + c];
        }
        __syncthreads();
#pragma unroll
        for (int it = 0; it < 4; it++) {
            int i = (tid >> 5) + it * 8, j = tid & 31;
            __nv_bfloat16 hv, lv;
            split1(s_tr[j][i], hv, lv);
            size_t dst = ((size_t)t * HID + ub + i) * 64 + bb + j;
            g_xhi[dst] = hv;
            g_xlo[dst] = lv;
        }
        __syncthreads();
    }
    // ======== phase 0b: W transpose + gate-permute + split ========
    // Wt[l][p][k] = W[l][k][n], p = ((n&1023)<<2) | (n>>10)
    for (int tile = bid; tile < 2 * 64 * 128; tile += NBLK) {
        const int l  = tile >> 13;
        const int kt = (tile & 8191) >> 7;
        const int nt = tile & 127;
        const int k0 = kt * 32, n0 = nt * 32;
#pragma unroll
        for (int r = 0; r < 4; r++) {
            int kk = (tid >> 5) + r * 8;
            s_tr[kk][lane] = W[((size_t)l * KTOT + k0 + kk) * NOUT + n0 + lane];
        }
        __syncthreads();
#pragma unroll
        for (int r = 0; r < 4; r++) {
            int j = (tid >> 5) + r * 8;
            int n = n0 + j;
            int p = ((n & 1023) << 2) | (n >> 10);
            __nv_bfloat16 hv, lv;
            split1(s_tr[lane][j], hv, lv);
            size_t dst = ((size_t)l * NOUT + p) * KTOT + k0 + lane;
            g_wthi[dst] = hv;
            g_wtlo[dst] = lv;
        }
        __syncthreads();
    }
    // ======== phase 0c: seed h (transposed, split) and c (transposed) =====
    for (int tile = bid; tile < 256; tile += NBLK) {
        const int kind = tile >> 7;
        const int rest = tile & 127;
        const int l  = rest >> 6;
        const int ut = (rest >> 1) & 31;
        const int bt = rest & 1;
        const int ub = ut * 32, bb = bt * 32;
        const float* src = (kind == 0) ? h0 : c0;
#pragma unroll
        for (int it = 0; it < 4; it++) {
            int r = (tid >> 5) + it * 8, c = tid & 31;
            s_tr[r][c] = src[((size_t)l * 64 + bb + r) * HID + ub + c];
        }
        __syncthreads();
#pragma unroll
        for (int it = 0; it < 4; it++) {
            int i = (tid >> 5) + it * 8, j = tid & 31;
            float v = s_tr[j][i];
            if (kind == 0) {
                __nv_bfloat16 hv, lv;
                split1(v, hv, lv);
                size_t dst = (size_t)l * BH + (size_t)(ub + i) * 64 + bb + j;
                g_hhi[dst] = hv;
                g_hlo[dst] = lv;
            } else {
                g_c[(size_t)l * BH + (size_t)(ub + i) * 64 + bb + j] = v;
            }
        }
        __syncthreads();
    }
    grid_barrier();

    // ---- lane-constant ldmatrix row bases + swizzle XORs ----
    // swz(row*128 + col) == row*128 + (col ^ ((row&7)*16))  for col < 128
    const int q  = lane >> 3, r8 = lane & 7;
    const int rowA = mw + r8 + (q & 1) * 8;           // 0..127 (A: [m][k])
    const uint32_t baseA = (uint32_t)rowA * 128;
    const uint32_t xorA  = (uint32_t)(rowA & 7) * 16;
    const int rowB = (q & 1) * 8 + r8;                // 0..15  (B: [k][b])
    const uint32_t baseB = (uint32_t)rowB * 128;
    const uint32_t xorB  = (uint32_t)(rowB & 7) * 16; // rowB +16/kk: &7 invariant
    const uint32_t colq  = (uint32_t)(q >> 1) * 16;

    // ---- cp.async issue helpers ----
    auto issueW = [&](const __nv_bfloat16* Wh, const __nv_bfloat16* Wo,
                      int kc, uint32_t st) {
#pragma unroll
        for (int it = 0; it < 4; it++) {
            int idx = tid + it * 256;
            uint32_t off = swz((idx >> 3) * 128 + (idx & 7) * 16);
            size_t go = (size_t)(idx >> 3) * KTOT + kc + (idx & 7) * 8;
            cpa16(st + off, Wh + go);
            cpa16(st + 16384 + off, Wo + go);
        }
    };
    auto issueB = [&](const __nv_bfloat16* Bh, const __nv_bfloat16* Bl,
                      int kc, uint32_t st) {
#pragma unroll
        for (int it = 0; it < 2; it++) {
            int idx = tid + it * 256;
            uint32_t off = swz((idx >> 3) * 128 + (idx & 7) * 16);
            size_t go = (size_t)(kc * 64) + (size_t)idx * 8;
            cpa16(st + 32768 + off, Bh + go);
            cpa16(st + 40960 + off, Bl + go);
        }
    };

    // ---- initial W prefetch for phase (t=0, l=0): chunks 0,1 (uncommitted)
    {
        const __nv_bfloat16* Wh = g_wthi + ((size_t)m0) * KTOT + ks * KSL;
        const __nv_bfloat16* Wo = g_wtlo + ((size_t)m0) * KTOT + ks * KSL;
        issueW(Wh, Wo, 0, sbase);
        issueW(Wh, Wo, CHK, sbase + STGB);
    }

    // ======== main recurrence ========
    for (int t = 0; t < SEQ; t++) {
        const int pin  = t & 1;
        const int pout = pin ^ 1;
#pragma unroll 1
        for (int l = 0; l < 2; l++) {
            const __nv_bfloat16* Wh = g_wthi + ((size_t)l * NOUT + m0) * KTOT + ks * KSL;
            const __nv_bfloat16* Wo = g_wtlo + ((size_t)l * NOUT + m0) * KTOT + ks * KSL;
            const __nv_bfloat16 *Bh, *Bl;
            if (l == 0) {
                if (ks < 2) {
                    Bh = g_xhi + ((size_t)t * HID + ks * KSL) * 64;
                    Bl = g_xlo + ((size_t)t * HID + ks * KSL) * 64;
                } else {
                    Bh = g_hhi + (size_t)(pin * 2 + 0) * BH + (size_t)(ks - 2) * KSL * 64;
                    Bl = g_hlo + (size_t)(pin * 2 + 0) * BH + (size_t)(ks - 2) * KSL * 64;
                }
            } else {
                if (ks < 2) {
                    Bh = g_hhi + (size_t)(pout * 2 + 0) * BH + (size_t)ks * KSL * 64;
                    Bl = g_hlo + (size_t)(pout * 2 + 0) * BH + (size_t)ks * KSL * 64;
                } else {
                    Bh = g_hhi + (size_t)(pin * 2 + 1) * BH + (size_t)(ks - 2) * KSL * 64;
                    Bl = g_hlo + (size_t)(pin * 2 + 1) * BH + (size_t)(ks - 2) * KSL * 64;
                }
            }

            float acc[8][4];
#pragma unroll
            for (int i = 0; i < 8; i++)
#pragma unroll
                for (int j = 0; j < 4; j++) acc[i][j] = 0.0f;

            // B for chunks 0,1 (W already prefetched across the barrier gap).
            // G0 = {W0, W1 (early), B0}; G1 = {B1}.
            issueB(Bh, Bl, 0, sbase);
            cpa_commit();
            issueB(Bh, Bl, CHK, sbase + STGB);
            cpa_commit();

            for (int ch = 0; ch < NCHK; ch++) {
                if (ch + 2 < NCHK) {     // issue chunk ch+2 (full W+B)
                    const uint32_t st = sbase + ((ch + 2) % NSTG) * STGB;
                    const int kc = (ch + 2) * CHK;
                    issueW(Wh, Wo, kc, st);
                    issueB(Bh, Bl, kc, st);
                    cpa_commit();
                    cpa_wait2();
                } else if (ch + 1 < NCHK) {
                    cpa_wait1();
                } else {
                    cpa_wait0();
                }
                __syncthreads();

                // ---- compute chunk ch ----
                const uint32_t st = sbase + (ch % NSTG) * STGB;
#pragma unroll
                for (int kk = 0; kk < 4; kk++) {
                    const uint32_t aoff = baseA + ((colq + kk * 32) ^ xorA);
                    uint32_t ahi[4], alo[4];
                    ldsm4(st + aoff, ahi[0], ahi[1], ahi[2], ahi[3]);
                    ldsm4(st + 16384 + aoff, alo[0], alo[1], alo[2], alo[3]);
#pragma unroll
                    for (int p = 0; p < 4; p++) {
                        const uint32_t boff = baseB + (uint32_t)kk * 2048
                                            + ((colq + p * 32) ^ xorB);
                        uint32_t bh[4], bl[4];
                        ldsm4t(st + 32768 + boff, bh[0], bh[1], bh[2], bh[3]);
                        ldsm4t(st + 40960 + boff, bl[0], bl[1], bl[2], bl[3]);
                        mma16816(acc[2 * p],     ahi, bh[0], bh[1]);
                        mma16816(acc[2 * p],     ahi, bl[0], bl[1]);
                        mma16816(acc[2 * p],     alo, bh[0], bh[1]);
                        mma16816(acc[2 * p + 1], ahi, bh[2], bh[3]);
                        mma16816(acc[2 * p + 1], ahi, bl[2], bl[3]);
                        mma16816(acc[2 * p + 1], alo, bh[2], bh[3]);
                    }
                }
                __syncthreads();
            }

            // ---- gap prefetch: next phase's W chunks 0,1 (layer 1-l) ----
            // Stages 0,1 held chunks NCHK-3, NCHK-1: both consumed + synced.
            {
                const __nv_bfloat16* nWh =
                    g_wthi + ((size_t)(1 - l) * NOUT + m0) * KTOT + ks * KSL;
                const __nv_bfloat16* nWo =
                    g_wtlo + ((size_t)(1 - l) * NOUT + m0) * KTOT + ks * KSL;
                issueW(nWh, nWo, 0, sbase);
                issueW(nWh, nWo, CHK, sbase + STGB);
            }

            // ---- epilogue: acc -> split-K partials ----
            {
                const int g  = lane >> 2;
                const int tt = lane & 3;
                float* base = g_partial + ((size_t)ks * NOUT + m0 + mw) * 64;
#pragma unroll
                for (int nt = 0; nt < 8; nt++) {
                    *reinterpret_cast<float2*>(base + (size_t)g * 64 + nt * 8 + 2 * tt) =
                        make_float2(acc[nt][0], acc[nt][1]);
                    *reinterpret_cast<float2*>(base + (size_t)(g + 8) * 64 + nt * 8 + 2 * tt) =
                        make_float2(acc[nt][2], acc[nt][3]);
                }
            }
            grid_barrier();

            // ---- cell phase: 8 units x 64 batches per CTA ----
            {
                const int b = tid & 63;
#pragma unroll
                for (int it2 = 0; it2 < 2; it2++) {
                    const int ul = (tid >> 6) + it2 * 4;
                    const int u = u0 + ul;
                    float gv[4];
#pragma unroll
                    for (int gate = 0; gate < 4; gate++) {
                        const int p = 4 * u + gate;
                        float s = bias[(size_t)l * NOUT + gate * 1024 + u];
#pragma unroll
                        for (int ksi = 0; ksi < NKS; ksi++)
                            s += g_partial[((size_t)ksi * NOUT + p) * 64 + b];
                        gv[gate] = s;
                    }
                    const size_t cidx = (size_t)l * BH + (size_t)u * 64 + b;
                    const float gi = sigmoidf_(gv[0]);
                    const float gj = tanhf(gv[1]);
                    const float gf = sigmoidf_(gv[2]);
                    const float go = sigmoidf_(gv[3]);
                    const float cn = g_c[cidx] * gf + gi * gj;
                    g_c[cidx] = cn;
                    const float hn = tanhf(cn) * go;
                    const size_t hidx = (size_t)(pout * 2 + l) * BH + (size_t)u * 64 + b;
                    g_hf[hidx] = hn;
                    __nv_bfloat16 hv, lv;
                    split1(hn, hv, lv);
                    g_hhi[hidx] = hv;
                    g_hlo[hidx] = lv;
                    s_hn[ul][b] = hn;
                }
                __syncthreads();
                if (l == 1 && tid < 64) {
                    const int b2 = tid;
                    float* op = out + (size_t)t * BH + (size_t)b2 * HID + u0;
                    reinterpret_cast<float4*>(op)[0] =
                        make_float4(s_hn[0][b2], s_hn[1][b2], s_hn[2][b2], s_hn[3][b2]);
                    reinterpret_cast<float4*>(op)[1] =
                        make_float4(s_hn[4][b2], s_hn[5][b2], s_hn[6][b2], s_hn[7][b2]);
                }
            }
            grid_barrier();
        }
    }

    // ======== tail: last_hidden (parity 0) + last_cell, de-transpose ======
    for (int i = gid; i < 2 * BH; i += GTH) {
        int l = i >> 16, rr = i & 65535, b = rr >> 10, u = rr & 1023;
        out[(size_t)SEQ * BH + i] = g_hf[(size_t)l * BH + (size_t)u * 64 + b];
        out[(size_t)SEQ * BH + 2 * BH + i] = g_c[(size_t)l * BH + (size_t)u * 64 + b];
    }
}

// ---------------- launch: ONE graph node ----------------
extern "C" void kernel_launch(void* const* d_in, const int* in_sizes, int n_in,
                              void* d_out, int out_size) {
    const float* input = (const float*)d_in[0];
    const float* h0    = (const float*)d_in[1];
    const float* c0    = (const float*)d_in[2];
    const float* W     = (const float*)d_in[3];
    const float* bias  = (const float*)d_in[4];
    float* out = (float*)d_out;

    cudaFuncSetAttribute(lstm_hmma, cudaFuncAttributeMaxDynamicSharedMemorySize, DSMEM);
    lstm_hmma<<<NBLK, NTHR, DSMEM>>>(input, h0, c0, W, bias, out);
}

// round 7
// speedup vs baseline: 1.0362x; 1.0362x over previous
#include <cuda_runtime.h>
#include <cuda_bf16.h>
#include <cstdint>

// BasicLSTM via mma.sync (HMMA bf16, 3-term fp32-split emulation).
// SEQ=512, BATCH=64, HID=1024, LAYERS=2.
// R7: 512 threads (16 warps), intra-CTA K-split (2 k-groups) with m32n32
// warp tiles -> LDS traffic 320->256 ldsm/chunk and 4 warps/SMSP for overlap.

#define SEQ    512
#define BATCH  64
#define HID    1024
#define KTOT   2048
#define NOUT   4096
#define BH     (BATCH * HID)        // 65536
#define NBLK   128
#define NTHR   512
#define GTH    (NBLK * NTHR)
#define NKS    4
#define KSL    512                  // K per slice
#define CHK    64                   // K per chunk
#define NCHK   (KSL / CHK)          // 8
#define STGB   49152                // Ahi16K | Alo16K | Bhi8K | Blo8K
#define NSTG   2
#define DSMEM  (NSTG * STGB)

// ---------------- device globals (no allocs) ----------------
__device__ __align__(128) __nv_bfloat16 g_xhi[(size_t)SEQ * HID * 64];
__device__ __align__(128) __nv_bfloat16 g_xlo[(size_t)SEQ * HID * 64];
__device__ __align__(128) __nv_bfloat16 g_wthi[(size_t)2 * NOUT * KTOT]; // [l][p][k]
__device__ __align__(128) __nv_bfloat16 g_wtlo[(size_t)2 * NOUT * KTOT];
__device__ __align__(128) __nv_bfloat16 g_hhi[4 * BH];   // [par*2+l][u][b]
__device__ __align__(128) __nv_bfloat16 g_hlo[4 * BH];
__device__ __align__(128) float g_partial[(size_t)NKS * NOUT * 64]; // [ks][p][b]
__device__ __align__(128) float g_c[2 * BH];              // [l][u][b]
__device__ __align__(128) float g_hf[4 * BH];             // [par*2+l][u][b]
__device__ unsigned g_bar_arrive;
__device__ unsigned g_bar_gen;

// ---------------- PTX helpers ----------------
__device__ __forceinline__ uint32_t smem_u32(const void* p) {
    uint32_t a;
    asm("{ .reg .u64 t; cvta.to.shared.u64 t, %1; cvt.u32.u64 %0, t; }"
        : "=r"(a) : "l"(p));
    return a;
}
__device__ __forceinline__ void cpa16(uint32_t s, const void* g) {
    asm volatile("cp.async.cg.shared.global [%0], [%1], 16;" :: "r"(s), "l"(g));
}
__device__ __forceinline__ void cpa_commit() {
    asm volatile("cp.async.commit_group;" ::: "memory");
}
__device__ __forceinline__ void cpa_wait1() {
    asm volatile("cp.async.wait_group 1;" ::: "memory");
}
__device__ __forceinline__ void cpa_wait0() {
    asm volatile("cp.async.wait_group 0;" ::: "memory");
}
__device__ __forceinline__ void ldsm4(uint32_t a, uint32_t* r) {
    asm volatile("ldmatrix.sync.aligned.m8n8.x4.shared.b16 {%0,%1,%2,%3}, [%4];"
                 : "=r"(r[0]), "=r"(r[1]), "=r"(r[2]), "=r"(r[3]) : "r"(a));
}
__device__ __forceinline__ void ldsm4t(uint32_t a, uint32_t* r) {
    asm volatile("ldmatrix.sync.aligned.m8n8.x4.trans.shared.b16 {%0,%1,%2,%3}, [%4];"
                 : "=r"(r[0]), "=r"(r[1]), "=r"(r[2]), "=r"(r[3]) : "r"(a));
}
__device__ __forceinline__ void mma16816(float* c, const uint32_t* a,
                                         uint32_t b0, uint32_t b1) {
    asm volatile("mma.sync.aligned.m16n8k16.row.col.f32.bf16.bf16.f32 "
                 "{%0,%1,%2,%3}, {%4,%5,%6,%7}, {%8,%9}, {%0,%1,%2,%3};"
                 : "+f"(c[0]), "+f"(c[1]), "+f"(c[2]), "+f"(c[3])
                 : "r"(a[0]), "r"(a[1]), "r"(a[2]), "r"(a[3]), "r"(b0), "r"(b1));
}
__device__ __forceinline__ float sigmoidf_(float x) { return 1.0f / (1.0f + expf(-x)); }
__device__ __forceinline__ void split1(float v, __nv_bfloat16& h, __nv_bfloat16& l) {
    h = __float2bfloat16_rn(v);
    l = __float2bfloat16_rn(v - __bfloat162float(h));
}
__device__ __forceinline__ uint32_t swz(uint32_t off) {
    return off ^ ((off >> 3) & 0x70);
}

// ---------------- grid barrier (all 128 blocks resident) ----------------
__device__ __forceinline__ void grid_barrier() {
    __syncthreads();
    if (threadIdx.x == 0) {
        __threadfence();
        unsigned gen = *((volatile unsigned*)&g_bar_gen);
        if (atomicAdd(&g_bar_arrive, 1u) == NBLK - 1) {
            g_bar_arrive = 0;
            __threadfence();
            atomicAdd(&g_bar_gen, 1u);
        } else {
            while (*((volatile unsigned*)&g_bar_gen) == gen) { __nanosleep(20); }
        }
        __threadfence();
    }
    __syncthreads();
}

// ---------------- persistent kernel ----------------
__global__ void __launch_bounds__(NTHR, 1)
lstm_hmma(const float* __restrict__ input,   // [512,64,1024]
          const float* __restrict__ h0,      // [2,64,1024]
          const float* __restrict__ c0,      // [2,64,1024]
          const float* __restrict__ W,       // [2,2048,4096]
          const float* __restrict__ bias,    // [2,4096]
          float* __restrict__ out)
{
    extern __shared__ __align__(1024) char dsm[];
    const uint32_t sbase = smem_u32(dsm);

    __shared__ float s_tr[32][33];
    __shared__ float s_hn[8][64];

    const int tid  = threadIdx.x;
    const int wid  = tid >> 5;
    const int lane = tid & 31;
    const int bid  = blockIdx.x;
    const int gid  = bid * NTHR + tid;
    const int cg   = bid & 31;        // M tile: rows [cg*128, +128)
    const int ks   = bid >> 5;        // K slice: [ks*512, +512)
    const int m0   = cg * 128;
    const int u0   = bid * 8;         // cell-owned units

    // warp mapping: kg = k-group (kk pair), wpos -> (mq, nh) m32n32 tile
    const int kg   = wid >> 3;        // 0: kk{0,1}, 1: kk{2,3}
    const int wpos = wid & 7;
    const int mq   = wpos >> 1;       // m offset mq*32
    const int nh   = wpos & 1;        // n offset nh*32

    // ======== phase 0a: x transpose [t][b][u] -> [t][u][b] + bf16 split ====
    for (int tile = bid; tile < SEQ * 64; tile += NBLK) {
        const int t  = tile >> 6;
        const int ut = (tile >> 1) & 31;
        const int bt = tile & 1;
        const int ub = ut * 32, bb = bt * 32;
#pragma unroll
        for (int it = 0; it < 2; it++) {
            int r = (tid >> 5) + it * 16, c = lane;
            s_tr[r][c] = input[((size_t)t * 64 + bb + r) * HID + ub + c];
        }
        __syncthreads();
#pragma unroll
        for (int it = 0; it < 2; it++) {
            int i = (tid >> 5) + it * 16, j = lane;
            __nv_bfloat16 hv, lv;
            split1(s_tr[j][i], hv, lv);
            size_t dst = ((size_t)t * HID + ub + i) * 64 + bb + j;
            g_xhi[dst] = hv;
            g_xlo[dst] = lv;
        }
        __syncthreads();
    }
    // ======== phase 0b: W transpose + gate-permute + split ========
    for (int tile = bid; tile < 2 * 64 * 128; tile += NBLK) {
        const int l  = tile >> 13;
        const int kt = (tile & 8191) >> 7;
        const int nt = tile & 127;
        const int k0 = kt * 32, n0 = nt * 32;
#pragma unroll
        for (int r = 0; r < 2; r++) {
            int kk = (tid >> 5) + r * 16;
            s_tr[kk][lane] = W[((size_t)l * KTOT + k0 + kk) * NOUT + n0 + lane];
        }
        __syncthreads();
#pragma unroll
        for (int r = 0; r < 2; r++) {
            int j = (tid >> 5) + r * 16;
            int n = n0 + j;
            int p = ((n & 1023) << 2) | (n >> 10);
            __nv_bfloat16 hv, lv;
            split1(s_tr[lane][j], hv, lv);
            size_t dst = ((size_t)l * NOUT + p) * KTOT + k0 + lane;
            g_wthi[dst] = hv;
            g_wtlo[dst] = lv;
        }
        __syncthreads();
    }
    // ======== phase 0c: seed h (transposed, split) and c (transposed) =====
    for (int tile = bid; tile < 256; tile += NBLK) {
        const int kind = tile >> 7;
        const int rest = tile & 127;
        const int l  = rest >> 6;
        const int ut = (rest >> 1) & 31;
        const int bt = rest & 1;
        const int ub = ut * 32, bb = bt * 32;
        const float* src = (kind == 0) ? h0 : c0;
#pragma unroll
        for (int it = 0; it < 2; it++) {
            int r = (tid >> 5) + it * 16, c = lane;
            s_tr[r][c] = src[((size_t)l * 64 + bb + r) * HID + ub + c];
        }
        __syncthreads();
#pragma unroll
        for (int it = 0; it < 2; it++) {
            int i = (tid >> 5) + it * 16, j = lane;
            float v = s_tr[j][i];
            if (kind == 0) {
                __nv_bfloat16 hv, lv;
                split1(v, hv, lv);
                size_t dst = (size_t)l * BH + (size_t)(ub + i) * 64 + bb + j;
                g_hhi[dst] = hv;
                g_hlo[dst] = lv;
            } else {
                g_c[(size_t)l * BH + (size_t)(ub + i) * 64 + bb + j] = v;
            }
        }
        __syncthreads();
    }
    grid_barrier();

    // ---- lane-constant ldmatrix row bases + swizzle XORs ----
    const int q  = lane >> 3, r8 = lane & 7;
    const int rowA = mq * 32 + r8 + (q & 1) * 8;      // mi=0; mi=1 adds 16 rows
    const uint32_t baseA = (uint32_t)rowA * 128;
    const uint32_t xorA  = (uint32_t)(rowA & 7) * 16; // +16 rows: &7 invariant
    const int rowB = (q & 1) * 8 + r8;
    const uint32_t baseB = (uint32_t)rowB * 128;
    const uint32_t xorB  = (uint32_t)(rowB & 7) * 16; // +16 rows/kk: invariant
    const uint32_t colq  = (uint32_t)(q >> 1) * 16;

    // ---- cp.async issue helpers (512 threads) ----
    auto issueW = [&](const __nv_bfloat16* Wh, const __nv_bfloat16* Wo,
                      int kc, uint32_t st) {
#pragma unroll
        for (int it = 0; it < 2; it++) {
            int idx = tid + it * 512;                  // 0..1023
            uint32_t off = swz((idx >> 3) * 128 + (idx & 7) * 16);
            size_t go = (size_t)(idx >> 3) * KTOT + kc + (idx & 7) * 8;
            cpa16(st + off, Wh + go);
            cpa16(st + 16384 + off, Wo + go);
        }
    };
    auto issueB = [&](const __nv_bfloat16* Bh, const __nv_bfloat16* Bl,
                      int kc, uint32_t st) {
        int idx = tid;                                 // 0..511
        uint32_t off = swz((idx >> 3) * 128 + (idx & 7) * 16);
        size_t go = (size_t)(kc * 64) + (size_t)idx * 8;
        cpa16(st + 32768 + off, Bh + go);
        cpa16(st + 40960 + off, Bl + go);
    };

    // ======== main recurrence ========
    for (int t = 0; t < SEQ; t++) {
        const int pin  = t & 1;
        const int pout = pin ^ 1;
#pragma unroll 1
        for (int l = 0; l < 2; l++) {
            const __nv_bfloat16* Wh = g_wthi + ((size_t)l * NOUT + m0) * KTOT + ks * KSL;
            const __nv_bfloat16* Wo = g_wtlo + ((size_t)l * NOUT + m0) * KTOT + ks * KSL;
            const __nv_bfloat16 *Bh, *Bl;
            if (l == 0) {
                if (ks < 2) {
                    Bh = g_xhi + ((size_t)t * HID + ks * KSL) * 64;
                    Bl = g_xlo + ((size_t)t * HID + ks * KSL) * 64;
                } else {
                    Bh = g_hhi + (size_t)(pin * 2 + 0) * BH + (size_t)(ks - 2) * KSL * 64;
                    Bl = g_hlo + (size_t)(pin * 2 + 0) * BH + (size_t)(ks - 2) * KSL * 64;
                }
            } else {
                if (ks < 2) {
                    Bh = g_hhi + (size_t)(pout * 2 + 0) * BH + (size_t)ks * KSL * 64;
                    Bl = g_hlo + (size_t)(pout * 2 + 0) * BH + (size_t)ks * KSL * 64;
                } else {
                    Bh = g_hhi + (size_t)(pin * 2 + 1) * BH + (size_t)(ks - 2) * KSL * 64;
                    Bl = g_hlo + (size_t)(pin * 2 + 1) * BH + (size_t)(ks - 2) * KSL * 64;
                }
            }

            float acc[2][4][4];    // [mi][n8 group][reg]
#pragma unroll
            for (int i = 0; i < 2; i++)
#pragma unroll
                for (int j = 0; j < 4; j++)
#pragma unroll
                    for (int r = 0; r < 4; r++) acc[i][j][r] = 0.0f;

            // issue chunk 0
            issueW(Wh, Wo, 0, sbase);
            issueB(Bh, Bl, 0, sbase);
            cpa_commit();

            for (int ch = 0; ch < NCHK; ch++) {
                if (ch < NCHK - 1) {     // issue chunk ch+1 into other stage
                    const uint32_t st = sbase + ((ch + 1) & 1) * STGB;
                    const int kc = (ch + 1) * CHK;
                    issueW(Wh, Wo, kc, st);
                    issueB(Bh, Bl, kc, st);
                    cpa_commit();
                    cpa_wait1();
                } else {
                    cpa_wait0();
                }
                __syncthreads();

                // ---- compute chunk ch (this warp's 2 kk of 4) ----
                const uint32_t st = sbase + (ch & 1) * STGB;
#pragma unroll
                for (int kk2 = 0; kk2 < 2; kk2++) {
                    const int kk = kg * 2 + kk2;
                    const uint32_t aoff = (colq + kk * 32) ^ xorA;
                    uint32_t ahi0[4], ahi1[4], alo0[4], alo1[4];
                    ldsm4(st + baseA + aoff, ahi0);
                    ldsm4(st + baseA + 2048 + aoff, ahi1);
                    ldsm4(st + 16384 + baseA + aoff, alo0);
                    ldsm4(st + 16384 + baseA + 2048 + aoff, alo1);
#pragma unroll
                    for (int pl = 0; pl < 2; pl++) {
                        const int p = nh * 2 + pl;
                        const uint32_t boff = baseB + (uint32_t)kk * 2048
                                            + ((colq + p * 32) ^ xorB);
                        uint32_t bh[4], bl[4];
                        ldsm4t(st + 32768 + boff, bh);
                        ldsm4t(st + 40960 + boff, bl);
                        mma16816(acc[0][2 * pl],     ahi0, bh[0], bh[1]);
                        mma16816(acc[0][2 * pl],     ahi0, bl[0], bl[1]);
                        mma16816(acc[0][2 * pl],     alo0, bh[0], bh[1]);
                        mma16816(acc[0][2 * pl + 1], ahi0, bh[2], bh[3]);
                        mma16816(acc[0][2 * pl + 1], ahi0, bl[2], bl[3]);
                        mma16816(acc[0][2 * pl + 1], alo0, bh[2], bh[3]);
                        mma16816(acc[1][2 * pl],     ahi1, bh[0], bh[1]);
                        mma16816(acc[1][2 * pl],     ahi1, bl[0], bl[1]);
                        mma16816(acc[1][2 * pl],     alo1, bh[0], bh[1]);
                        mma16816(acc[1][2 * pl + 1], ahi1, bh[2], bh[3]);
                        mma16816(acc[1][2 * pl + 1], ahi1, bl[2], bl[3]);
                        mma16816(acc[1][2 * pl + 1], alo1, bh[2], bh[3]);
                    }
                }
                __syncthreads();
            }

            // ---- k-group reduction via (reused) stage smem ----
            if (kg == 1) {
                const uint32_t rb = sbase + (uint32_t)wpos * 4096 + (uint32_t)lane * 4;
#pragma unroll
                for (int i = 0; i < 2; i++)
#pragma unroll
                    for (int j = 0; j < 4; j++)
#pragma unroll
                        for (int r = 0; r < 4; r++) {
                            asm volatile("st.shared.b32 [%0], %1;"
                                :: "r"(rb + ((i * 4 + j) * 4 + r) * 128),
                                   "f"(acc[i][j][r]) : "memory");
                        }
            }
            __syncthreads();

            // ---- epilogue: kg0 adds kg1's acc, writes split-K partials ----
            if (kg == 0) {
                const uint32_t rb = sbase + (uint32_t)wpos * 4096 + (uint32_t)lane * 4;
                const int g4 = lane >> 2;
                const int tt = lane & 3;
#pragma unroll
                for (int i = 0; i < 2; i++) {
#pragma unroll
                    for (int j = 0; j < 4; j++) {
                        float o[4];
#pragma unroll
                        for (int r = 0; r < 4; r++) {
                            float v;
                            asm volatile("ld.shared.b32 %0, [%1];"
                                : "=f"(v)
                                : "r"(rb + ((i * 4 + j) * 4 + r) * 128));
                            o[r] = acc[i][j][r] + v;
                        }
                        const int prow = m0 + mq * 32 + i * 16 + g4;
                        const int col  = nh * 32 + j * 8 + 2 * tt;
                        float* pp = g_partial + ((size_t)ks * NOUT + prow) * 64 + col;
                        *reinterpret_cast<float2*>(pp) = make_float2(o[0], o[1]);
                        *reinterpret_cast<float2*>(pp + 8 * 64) = make_float2(o[2], o[3]);
                    }
                }
            }
            grid_barrier();

            // ---- cell phase: 8 units x 64 batches per CTA (512 threads) ----
            {
                const int b  = tid & 63;
                const int ul = tid >> 6;            // 0..7
                const int u  = u0 + ul;
                float gv[4];
#pragma unroll
                for (int gate = 0; gate < 4; gate++) {
                    const int p = 4 * u + gate;
                    float s = bias[(size_t)l * NOUT + gate * 1024 + u];
#pragma unroll
                    for (int ksi = 0; ksi < NKS; ksi++)
                        s += g_partial[((size_t)ksi * NOUT + p) * 64 + b];
                    gv[gate] = s;
                }
                const size_t cidx = (size_t)l * BH + (size_t)u * 64 + b;
                const float gi = sigmoidf_(gv[0]);
                const float gj = tanhf(gv[1]);
                const float gf = sigmoidf_(gv[2]);
                const float go = sigmoidf_(gv[3]);
                const float cn = g_c[cidx] * gf + gi * gj;
                g_c[cidx] = cn;
                const float hn = tanhf(cn) * go;
                const size_t hidx = (size_t)(pout * 2 + l) * BH + (size_t)u * 64 + b;
                g_hf[hidx] = hn;
                __nv_bfloat16 hv, lv;
                split1(hn, hv, lv);
                g_hhi[hidx] = hv;
                g_hlo[hidx] = lv;
                s_hn[ul][b] = hn;
                __syncthreads();
                if (l == 1 && tid < 64) {
                    const int b2 = tid;
                    float* op = out + (size_t)t * BH + (size_t)b2 * HID + u0;
                    reinterpret_cast<float4*>(op)[0] =
                        make_float4(s_hn[0][b2], s_hn[1][b2], s_hn[2][b2], s_hn[3][b2]);
                    reinterpret_cast<float4*>(op)[1] =
                        make_float4(s_hn[4][b2], s_hn[5][b2], s_hn[6][b2], s_hn[7][b2]);
                }
            }
            grid_barrier();
        }
    }

    // ======== tail: last_hidden (parity 0) + last_cell, de-transpose ======
    for (int i = gid; i < 2 * BH; i += GTH) {
        int l = i >> 16, rr = i & 65535, b = rr >> 10, u = rr & 1023;
        out[(size_t)SEQ * BH + i] = g_hf[(size_t)l * BH + (size_t)u * 64 + b];
        out[(size_t)SEQ * BH + 2 * BH + i] = g_c[(size_t)l * BH + (size_t)u * 64 + b];
    }
}

// ---------------- launch: ONE graph node ----------------
extern "C" void kernel_launch(void* const* d_in, const int* in_sizes, int n_in,
                              void* d_out, int out_size) {
    const float* input = (const float*)d_in[0];
    const float* h0    = (const float*)d_in[1];
    const float* c0    = (const float*)d_in[2];
    const float* W     = (const float*)d_in[3];
    const float* bias  = (const float*)d_in[4];
    float* out = (float*)d_out;

    cudaFuncSetAttribute(lstm_hmma, cudaFuncAttributeMaxDynamicSharedMemorySize, DSMEM);
    lstm_hmma<<<NBLK, NTHR, DSMEM>>>(input, h0, c0, W, bias, out);
}

// round 8
// speedup vs baseline: 1.2950x; 1.2497x over previous
#include <cuda_runtime.h>
#include <cuda_bf16.h>
#include <cstdint>

// BasicLSTM via mma.sync (HMMA bf16, 3-term fp32-split emulation).
// SEQ=512, BATCH=64, HID=1024, LAYERS=2.
// R8: wavefront layer pipelining. One super-step s computes layer0@s (CTAs
// 0-63) and layer1@(s-1) (CTAs 64-127) concurrently -> 513 super-steps,
// 2 grid barriers each (vs 2048 phases x 2 before). Split-K=2 per layer.

#define SEQ    512
#define BATCH  64
#define HID    1024
#define KTOT   2048
#define NOUT   4096
#define BH     (BATCH * HID)        // 65536
#define NBLK   128
#define NTHR   512
#define GTH    (NBLK * NTHR)
#define KSL    1024                 // K per slice (2 slices per layer)
#define CHK    64                   // K per chunk
#define NCHK   (KSL / CHK)          // 16
#define STGB   49152                // Ahi16K | Alo16K | Bhi8K | Blo8K
#define NSTG   2
#define DSMEM  (NSTG * STGB)

// ---------------- device globals (no allocs) ----------------
__device__ __align__(128) __nv_bfloat16 g_xhi[(size_t)SEQ * HID * 64];
__device__ __align__(128) __nv_bfloat16 g_xlo[(size_t)SEQ * HID * 64];
__device__ __align__(128) __nv_bfloat16 g_wthi[(size_t)2 * NOUT * KTOT]; // [l][p][k]
__device__ __align__(128) __nv_bfloat16 g_wtlo[(size_t)2 * NOUT * KTOT];
__device__ __align__(128) __nv_bfloat16 g_hhi[2 * BH];    // [l][u][b] single-buffered
__device__ __align__(128) __nv_bfloat16 g_hlo[2 * BH];
__device__ __align__(128) float g_partial[(size_t)4 * NOUT * 64]; // [lay*2+ks][p][b]
__device__ __align__(128) float g_c[2 * BH];              // [l][u][b]
__device__ __align__(128) float g_hf[2 * BH];             // [l][u][b]
__device__ unsigned g_bar_arrive;
__device__ unsigned g_bar_gen;

// ---------------- PTX helpers ----------------
__device__ __forceinline__ uint32_t smem_u32(const void* p) {
    uint32_t a;
    asm("{ .reg .u64 t; cvta.to.shared.u64 t, %1; cvt.u32.u64 %0, t; }"
        : "=r"(a) : "l"(p));
    return a;
}
__device__ __forceinline__ void cpa16(uint32_t s, const void* g) {
    asm volatile("cp.async.cg.shared.global [%0], [%1], 16;" :: "r"(s), "l"(g));
}
__device__ __forceinline__ void cpa_commit() {
    asm volatile("cp.async.commit_group;" ::: "memory");
}
__device__ __forceinline__ void cpa_wait1() {
    asm volatile("cp.async.wait_group 1;" ::: "memory");
}
__device__ __forceinline__ void cpa_wait0() {
    asm volatile("cp.async.wait_group 0;" ::: "memory");
}
__device__ __forceinline__ void ldsm4(uint32_t a, uint32_t* r) {
    asm volatile("ldmatrix.sync.aligned.m8n8.x4.shared.b16 {%0,%1,%2,%3}, [%4];"
                 : "=r"(r[0]), "=r"(r[1]), "=r"(r[2]), "=r"(r[3]) : "r"(a));
}
__device__ __forceinline__ void ldsm4t(uint32_t a, uint32_t* r) {
    asm volatile("ldmatrix.sync.aligned.m8n8.x4.trans.shared.b16 {%0,%1,%2,%3}, [%4];"
                 : "=r"(r[0]), "=r"(r[1]), "=r"(r[2]), "=r"(r[3]) : "r"(a));
}
__device__ __forceinline__ void mma16816(float* c, const uint32_t* a,
                                         uint32_t b0, uint32_t b1) {
    asm volatile("mma.sync.aligned.m16n8k16.row.col.f32.bf16.bf16.f32 "
                 "{%0,%1,%2,%3}, {%4,%5,%6,%7}, {%8,%9}, {%0,%1,%2,%3};"
                 : "+f"(c[0]), "+f"(c[1]), "+f"(c[2]), "+f"(c[3])
                 : "r"(a[0]), "r"(a[1]), "r"(a[2]), "r"(a[3]), "r"(b0), "r"(b1));
}
__device__ __forceinline__ float sigmoidf_(float x) { return 1.0f / (1.0f + expf(-x)); }
__device__ __forceinline__ void split1(float v, __nv_bfloat16& h, __nv_bfloat16& l) {
    h = __float2bfloat16_rn(v);
    l = __float2bfloat16_rn(v - __bfloat162float(h));
}
__device__ __forceinline__ uint32_t swz(uint32_t off) {
    return off ^ ((off >> 3) & 0x70);
}

// ---------------- grid barrier (all 128 blocks resident) ----------------
__device__ __forceinline__ void grid_barrier() {
    __syncthreads();
    if (threadIdx.x == 0) {
        __threadfence();
        unsigned gen = *((volatile unsigned*)&g_bar_gen);
        if (atomicAdd(&g_bar_arrive, 1u) == NBLK - 1) {
            g_bar_arrive = 0;
            __threadfence();
            atomicAdd(&g_bar_gen, 1u);
        } else {
            while (*((volatile unsigned*)&g_bar_gen) == gen) { __nanosleep(20); }
        }
        __threadfence();
    }
    __syncthreads();
}

// ---------------- persistent kernel ----------------
__global__ void __launch_bounds__(NTHR, 1)
lstm_hmma(const float* __restrict__ input,   // [512,64,1024]
          const float* __restrict__ h0,      // [2,64,1024]
          const float* __restrict__ c0,      // [2,64,1024]
          const float* __restrict__ W,       // [2,2048,4096]
          const float* __restrict__ bias,    // [2,4096]
          float* __restrict__ out)
{
    extern __shared__ __align__(1024) char dsm[];
    const uint32_t sbase = smem_u32(dsm);

    __shared__ float s_tr[32][33];
    __shared__ float s_hn[8][64];

    const int tid  = threadIdx.x;
    const int wid  = tid >> 5;
    const int lane = tid & 31;
    const int bid  = blockIdx.x;
    const int gid  = bid * NTHR + tid;
    const int lay  = bid >> 6;        // 0: layer0@s, 1: layer1@(s-1)
    const int cg   = bid & 31;        // M tile: rows [cg*128, +128)
    const int ks   = (bid >> 5) & 1;  // K slice: [ks*1024, +1024)
    const int pgrp = bid >> 5;        // partial group: lay*2+ks
    const int m0   = cg * 128;
    const int u0   = bid * 8;         // cell-owned units (both layers)

    // warp mapping: kg = k-group (kk pair), wpos -> (mq, nh) m32n32 tile
    const int kg   = wid >> 3;        // 0: kk{0,1}, 1: kk{2,3}
    const int wpos = wid & 7;
    const int mq   = wpos >> 1;       // m offset mq*32
    const int nh   = wpos & 1;        // n offset nh*32

    // ======== phase 0a: x transpose [t][b][u] -> [t][u][b] + bf16 split ====
    for (int tile = bid; tile < SEQ * 64; tile += NBLK) {
        const int t  = tile >> 6;
        const int ut = (tile >> 1) & 31;
        const int bt = tile & 1;
        const int ub = ut * 32, bb = bt * 32;
#pragma unroll
        for (int it = 0; it < 2; it++) {
            int r = (tid >> 5) + it * 16, c = lane;
            s_tr[r][c] = input[((size_t)t * 64 + bb + r) * HID + ub + c];
        }
        __syncthreads();
#pragma unroll
        for (int it = 0; it < 2; it++) {
            int i = (tid >> 5) + it * 16, j = lane;
            __nv_bfloat16 hv, lv;
            split1(s_tr[j][i], hv, lv);
            size_t dst = ((size_t)t * HID + ub + i) * 64 + bb + j;
            g_xhi[dst] = hv;
            g_xlo[dst] = lv;
        }
        __syncthreads();
    }
    // ======== phase 0b: W transpose + gate-permute + split ========
    for (int tile = bid; tile < 2 * 64 * 128; tile += NBLK) {
        const int l  = tile >> 13;
        const int kt = (tile & 8191) >> 7;
        const int nt = tile & 127;
        const int k0 = kt * 32, n0 = nt * 32;
#pragma unroll
        for (int r = 0; r < 2; r++) {
            int kk = (tid >> 5) + r * 16;
            s_tr[kk][lane] = W[((size_t)l * KTOT + k0 + kk) * NOUT + n0 + lane];
        }
        __syncthreads();
#pragma unroll
        for (int r = 0; r < 2; r++) {
            int j = (tid >> 5) + r * 16;
            int n = n0 + j;
            int p = ((n & 1023) << 2) | (n >> 10);
            __nv_bfloat16 hv, lv;
            split1(s_tr[lane][j], hv, lv);
            size_t dst = ((size_t)l * NOUT + p) * KTOT + k0 + lane;
            g_wthi[dst] = hv;
            g_wtlo[dst] = lv;
        }
        __syncthreads();
    }
    // ======== phase 0c: seed h (transposed, split) and c (transposed) =====
    for (int tile = bid; tile < 256; tile += NBLK) {
        const int kind = tile >> 7;
        const int rest = tile & 127;
        const int l  = rest >> 6;
        const int ut = (rest >> 1) & 31;
        const int bt = rest & 1;
        const int ub = ut * 32, bb = bt * 32;
        const float* src = (kind == 0) ? h0 : c0;
#pragma unroll
        for (int it = 0; it < 2; it++) {
            int r = (tid >> 5) + it * 16, c = lane;
            s_tr[r][c] = src[((size_t)l * 64 + bb + r) * HID + ub + c];
        }
        __syncthreads();
#pragma unroll
        for (int it = 0; it < 2; it++) {
            int i = (tid >> 5) + it * 16, j = lane;
            float v = s_tr[j][i];
            if (kind == 0) {
                __nv_bfloat16 hv, lv;
                split1(v, hv, lv);
                size_t dst = (size_t)l * BH + (size_t)(ub + i) * 64 + bb + j;
                g_hhi[dst] = hv;
                g_hlo[dst] = lv;
            } else {
                g_c[(size_t)l * BH + (size_t)(ub + i) * 64 + bb + j] = v;
            }
        }
        __syncthreads();
    }
    grid_barrier();

    // ---- lane-constant ldmatrix row bases + swizzle XORs ----
    const int q  = lane >> 3, r8 = lane & 7;
    const int rowA = mq * 32 + r8 + (q & 1) * 8;
    const uint32_t baseA = (uint32_t)rowA * 128;
    const uint32_t xorA  = (uint32_t)(rowA & 7) * 16;
    const int rowB = (q & 1) * 8 + r8;
    const uint32_t baseB = (uint32_t)rowB * 128;
    const uint32_t xorB  = (uint32_t)(rowB & 7) * 16;
    const uint32_t colq  = (uint32_t)(q >> 1) * 16;

    // ---- cp.async issue helpers (512 threads) ----
    auto issueW = [&](const __nv_bfloat16* Wh, const __nv_bfloat16* Wo,
                      int kc, uint32_t st) {
#pragma unroll
        for (int it = 0; it < 2; it++) {
            int idx = tid + it * 512;
            uint32_t off = swz((idx >> 3) * 128 + (idx & 7) * 16);
            size_t go = (size_t)(idx >> 3) * KTOT + kc + (idx & 7) * 8;
            cpa16(st + off, Wh + go);
            cpa16(st + 16384 + off, Wo + go);
        }
    };
    auto issueB = [&](const __nv_bfloat16* Bh, const __nv_bfloat16* Bl,
                      int kc, uint32_t st) {
        int idx = tid;
        uint32_t off = swz((idx >> 3) * 128 + (idx & 7) * 16);
        size_t go = (size_t)(kc * 64) + (size_t)idx * 8;
        cpa16(st + 32768 + off, Bh + go);
        cpa16(st + 40960 + off, Bl + go);
    };

    // W pointer fixed for this CTA
    const __nv_bfloat16* Wh = g_wthi + ((size_t)lay * NOUT + m0) * KTOT + ks * KSL;
    const __nv_bfloat16* Wo = g_wtlo + ((size_t)lay * NOUT + m0) * KTOT + ks * KSL;

    // ======== main recurrence: 513 super-steps ========
    for (int s = 0; s <= SEQ; s++) {
        const bool do_l0 = (s < SEQ);
        const bool do_l1 = (s >= 1);
        const bool active = (lay == 0) ? do_l0 : do_l1;

        if (active) {
            // ---- B operand selection ----
            const __nv_bfloat16 *Bh, *Bl;
            if (lay == 0) {
                if (ks == 0) { Bh = g_xhi + (size_t)s * BH; Bl = g_xlo + (size_t)s * BH; }
                else         { Bh = g_hhi;                  Bl = g_hlo; }
            } else {
                if (ks == 0) { Bh = g_hhi;      Bl = g_hlo; }
                else         { Bh = g_hhi + BH; Bl = g_hlo + BH; }
            }

            float acc[2][4][4];
#pragma unroll
            for (int i = 0; i < 2; i++)
#pragma unroll
                for (int j = 0; j < 4; j++)
#pragma unroll
                    for (int r = 0; r < 4; r++) acc[i][j][r] = 0.0f;

            issueW(Wh, Wo, 0, sbase);
            issueB(Bh, Bl, 0, sbase);
            cpa_commit();

            for (int ch = 0; ch < NCHK; ch++) {
                if (ch < NCHK - 1) {
                    const uint32_t st = sbase + ((ch + 1) & 1) * STGB;
                    const int kc = (ch + 1) * CHK;
                    issueW(Wh, Wo, kc, st);
                    issueB(Bh, Bl, kc, st);
                    cpa_commit();
                    cpa_wait1();
                } else {
                    cpa_wait0();
                }
                __syncthreads();

                const uint32_t st = sbase + (ch & 1) * STGB;
#pragma unroll
                for (int kk2 = 0; kk2 < 2; kk2++) {
                    const int kk = kg * 2 + kk2;
                    const uint32_t aoff = (colq + kk * 32) ^ xorA;
                    uint32_t ahi0[4], ahi1[4], alo0[4], alo1[4];
                    ldsm4(st + baseA + aoff, ahi0);
                    ldsm4(st + baseA + 2048 + aoff, ahi1);
                    ldsm4(st + 16384 + baseA + aoff, alo0);
                    ldsm4(st + 16384 + baseA + 2048 + aoff, alo1);
#pragma unroll
                    for (int pl = 0; pl < 2; pl++) {
                        const int p = nh * 2 + pl;
                        const uint32_t boff = baseB + (uint32_t)kk * 2048
                                            + ((colq + p * 32) ^ xorB);
                        uint32_t bh[4], bl[4];
                        ldsm4t(st + 32768 + boff, bh);
                        ldsm4t(st + 40960 + boff, bl);
                        mma16816(acc[0][2 * pl],     ahi0, bh[0], bh[1]);
                        mma16816(acc[0][2 * pl],     ahi0, bl[0], bl[1]);
                        mma16816(acc[0][2 * pl],     alo0, bh[0], bh[1]);
                        mma16816(acc[0][2 * pl + 1], ahi0, bh[2], bh[3]);
                        mma16816(acc[0][2 * pl + 1], ahi0, bl[2], bl[3]);
                        mma16816(acc[0][2 * pl + 1], alo0, bh[2], bh[3]);
                        mma16816(acc[1][2 * pl],     ahi1, bh[0], bh[1]);
                        mma16816(acc[1][2 * pl],     ahi1, bl[0], bl[1]);
                        mma16816(acc[1][2 * pl],     alo1, bh[0], bh[1]);
                        mma16816(acc[1][2 * pl + 1], ahi1, bh[2], bh[3]);
                        mma16816(acc[1][2 * pl + 1], ahi1, bl[2], bl[3]);
                        mma16816(acc[1][2 * pl + 1], alo1, bh[2], bh[3]);
                    }
                }
                __syncthreads();
            }

            // ---- k-group reduction via (reused) stage-0 smem ----
            if (kg == 1) {
                const uint32_t rb = sbase + (uint32_t)wpos * 4096 + (uint32_t)lane * 4;
#pragma unroll
                for (int i = 0; i < 2; i++)
#pragma unroll
                    for (int j = 0; j < 4; j++)
#pragma unroll
                        for (int r = 0; r < 4; r++) {
                            asm volatile("st.shared.b32 [%0], %1;"
                                :: "r"(rb + ((i * 4 + j) * 4 + r) * 128),
                                   "f"(acc[i][j][r]) : "memory");
                        }
            }
            __syncthreads();

            if (kg == 0) {
                const uint32_t rb = sbase + (uint32_t)wpos * 4096 + (uint32_t)lane * 4;
                const int g4 = lane >> 2;
                const int tt = lane & 3;
#pragma unroll
                for (int i = 0; i < 2; i++) {
#pragma unroll
                    for (int j = 0; j < 4; j++) {
                        float o[4];
#pragma unroll
                        for (int r = 0; r < 4; r++) {
                            float v;
                            asm volatile("ld.shared.b32 %0, [%1];"
                                : "=f"(v)
                                : "r"(rb + ((i * 4 + j) * 4 + r) * 128));
                            o[r] = acc[i][j][r] + v;
                        }
                        const int prow = m0 + mq * 32 + i * 16 + g4;
                        const int col  = nh * 32 + j * 8 + 2 * tt;
                        float* pp = g_partial + ((size_t)pgrp * NOUT + prow) * 64 + col;
                        *reinterpret_cast<float2*>(pp) = make_float2(o[0], o[1]);
                        *reinterpret_cast<float2*>(pp + 8 * 64) = make_float2(o[2], o[3]);
                    }
                }
            }
        }
        grid_barrier();

        // ---- cell phase: both layers, 8 units x 64 batches per CTA ----
        {
            const int b  = tid & 63;
            const int ul = tid >> 6;            // 0..7
            const int u  = u0 + ul;
#pragma unroll
            for (int cl = 0; cl < 2; cl++) {
                if (cl == 0 ? !do_l0 : !do_l1) continue;
                float gv[4];
#pragma unroll
                for (int gate = 0; gate < 4; gate++) {
                    const int p = 4 * u + gate;
                    float sum = bias[(size_t)cl * NOUT + gate * 1024 + u];
                    sum += g_partial[((size_t)(cl * 2 + 0) * NOUT + p) * 64 + b];
                    sum += g_partial[((size_t)(cl * 2 + 1) * NOUT + p) * 64 + b];
                    gv[gate] = sum;
                }
                const size_t cidx = (size_t)cl * BH + (size_t)u * 64 + b;
                const float gi = sigmoidf_(gv[0]);
                const float gj = tanhf(gv[1]);
                const float gf = sigmoidf_(gv[2]);
                const float go = sigmoidf_(gv[3]);
                const float cn = g_c[cidx] * gf + gi * gj;
                g_c[cidx] = cn;
                const float hn = tanhf(cn) * go;
                g_hf[cidx] = hn;
                __nv_bfloat16 hv, lv;
                split1(hn, hv, lv);
                g_hhi[cidx] = hv;
                g_hlo[cidx] = lv;
                if (cl == 1) s_hn[ul][b] = hn;
            }
            __syncthreads();
            if (do_l1 && tid < 64) {
                const int b2 = tid;
                float* op = out + (size_t)(s - 1) * BH + (size_t)b2 * HID + u0;
                reinterpret_cast<float4*>(op)[0] =
                    make_float4(s_hn[0][b2], s_hn[1][b2], s_hn[2][b2], s_hn[3][b2]);
                reinterpret_cast<float4*>(op)[1] =
                    make_float4(s_hn[4][b2], s_hn[5][b2], s_hn[6][b2], s_hn[7][b2]);
            }
        }
        grid_barrier();
    }

    // ======== tail: last_hidden + last_cell, de-transpose ========
    for (int i = gid; i < 2 * BH; i += GTH) {
        int l = i >> 16, rr = i & 65535, b = rr >> 10, u = rr & 1023;
        out[(size_t)SEQ * BH + i] = g_hf[(size_t)l * BH + (size_t)u * 64 + b];
        out[(size_t)SEQ * BH + 2 * BH + i] = g_c[(size_t)l * BH + (size_t)u * 64 + b];
    }
}

// ---------------- launch: ONE graph node ----------------
extern "C" void kernel_launch(void* const* d_in, const int* in_sizes, int n_in,
                              void* d_out, int out_size) {
    const float* input = (const float*)d_in[0];
    const float* h0    = (const float*)d_in[1];
    const float* c0    = (const float*)d_in[2];
    const float* W     = (const float*)d_in[3];
    const float* bias  = (const float*)d_in[4];
    float* out = (float*)d_out;

    cudaFuncSetAttribute(lstm_hmma, cudaFuncAttributeMaxDynamicSharedMemorySize, DSMEM);
    lstm_hmma<<<NBLK, NTHR, DSMEM>>>(input, h0, c0, W, bias, out);
}